// round 7
// baseline (speedup 1.0000x reference)
#include <cuda_runtime.h>
#include <cuda_bf16.h>
#include <cstdint>

#define N_NODES 100000
#define N_EDGES 1600000
#define IN_DIM 128
#define HID_DIM 256
#define LN_EPS 1e-5f

// ---------------- scratch (device globals: no runtime allocation) ----------
__device__ float4 g_h4[N_NODES * (IN_DIM / 4)];    // h = features * norm_src
__device__ float4 g_agg4[N_NODES * (IN_DIM / 4)];  // segsum(h[src],dst)*norm_dst
__device__ int g_deg_out[N_NODES];
__device__ int g_deg_in[N_NODES];
__device__ int g_row_start[N_NODES];               // CSR row offsets (by dst)
__device__ int g_cursor[N_NODES];                  // fill cursors
__device__ int g_col[N_EDGES];                     // CSR col = src node ids

// ---------------- K0: zero counters ----------------------------------------
__global__ void k_zero() {
    int i = blockIdx.x * blockDim.x + threadIdx.x;
    if (i < N_NODES) { g_deg_out[i] = 0; g_deg_in[i] = 0; g_cursor[i] = 0; }
}

// ---------------- K1: degree histograms (2 edges/thread, int32 indices) ----
__global__ void k_degree(const int* __restrict__ src,
                         const int* __restrict__ dst) {
    int t = blockIdx.x * blockDim.x + threadIdx.x;
    if (t * 2 >= N_EDGES) return;
    int2 s2 = reinterpret_cast<const int2*>(src)[t];
    int2 d2 = reinterpret_cast<const int2*>(dst)[t];
    atomicAdd(&g_deg_out[s2.x], 1);
    atomicAdd(&g_deg_out[s2.y], 1);
    atomicAdd(&g_deg_in[d2.x], 1);
    atomicAdd(&g_deg_in[d2.y], 1);
}

// ---------------- K2: exclusive scan of deg_in -> row_start (1 block) -------
__global__ __launch_bounds__(1024) void k_scan() {
    __shared__ int s_part[1024];
    const int CH = (N_NODES + 1023) / 1024;  // 98
    int tid = threadIdx.x;
    int begin = tid * CH;
    int end = begin + CH; if (end > N_NODES) end = N_NODES;
    int sum = 0;
    for (int i = begin; i < end; i++) sum += g_deg_in[i];
    s_part[tid] = sum;
    __syncthreads();
    // Hillis-Steele inclusive scan over 1024 partials
    for (int off = 1; off < 1024; off <<= 1) {
        int t = (tid >= off) ? s_part[tid - off] : 0;
        __syncthreads();
        if (tid >= off) s_part[tid] += t;
        __syncthreads();
    }
    int run = s_part[tid] - sum;  // exclusive prefix at chunk start
    for (int i = begin; i < end; i++) {
        g_row_start[i] = run;
        run += g_deg_in[i];
    }
}

// ---------------- K3: CSR fill (2 edges/thread, int atomics) ----------------
__global__ void k_fill(const int* __restrict__ src,
                       const int* __restrict__ dst) {
    int t = blockIdx.x * blockDim.x + threadIdx.x;
    if (t * 2 >= N_EDGES) return;
    int2 s2 = reinterpret_cast<const int2*>(src)[t];
    int2 d2 = reinterpret_cast<const int2*>(dst)[t];
    int p0 = atomicAdd(&g_cursor[d2.x], 1);
    int p1 = atomicAdd(&g_cursor[d2.y], 1);
    g_col[g_row_start[d2.x] + p0] = s2.x;
    g_col[g_row_start[d2.y] + p1] = s2.y;
}

// ---------------- K4: h = features * rsqrt(max(deg_out,1)) ------------------
__global__ void k_scale(const float* __restrict__ features) {
    int i = blockIdx.x * blockDim.x + threadIdx.x;  // one float4 per thread
    const int total = N_NODES * (IN_DIM / 4);
    if (i >= total) return;
    int node = i >> 5;  // 32 float4 per row
    float ns = rsqrtf(fmaxf((float)g_deg_out[node], 1.0f));
    const float4* f4 = reinterpret_cast<const float4*>(features);
    float4 v = f4[i];
    v.x *= ns; v.y *= ns; v.z *= ns; v.w *= ns;
    g_h4[i] = v;
}

// ---------------- K5: gather SpMM, warp per dst node ------------------------
// agg[n] = norm_dst[n] * sum_{e in row(n)} h[col[e]];  no float atomics.
__global__ __launch_bounds__(256) void k_gather() {
    int warp = (blockIdx.x * blockDim.x + threadIdx.x) >> 5;
    int lane = threadIdx.x & 31;
    if (warp >= N_NODES) return;
    int deg = g_deg_in[warp];
    int base = g_row_start[warp];
    float4 acc = make_float4(0.f, 0.f, 0.f, 0.f);
    int k = 0;
    for (; k + 4 <= deg; k += 4) {
        // Broadcast loads of 4 edge ids, then 4 independent gathers (MLP=4).
        int e0 = g_col[base + k];
        int e1 = g_col[base + k + 1];
        int e2 = g_col[base + k + 2];
        int e3 = g_col[base + k + 3];
        float4 a = g_h4[(size_t)e0 * 32 + lane];
        float4 b = g_h4[(size_t)e1 * 32 + lane];
        float4 c = g_h4[(size_t)e2 * 32 + lane];
        float4 d = g_h4[(size_t)e3 * 32 + lane];
        acc.x += (a.x + b.x) + (c.x + d.x);
        acc.y += (a.y + b.y) + (c.y + d.y);
        acc.z += (a.z + b.z) + (c.z + d.z);
        acc.w += (a.w + b.w) + (c.w + d.w);
    }
    for (; k < deg; k++) {
        int e = g_col[base + k];
        float4 a = g_h4[(size_t)e * 32 + lane];
        acc.x += a.x; acc.y += a.y; acc.z += a.z; acc.w += a.w;
    }
    float nd = rsqrtf(fmaxf((float)deg, 1.0f));
    acc.x *= nd; acc.y *= nd; acc.z *= nd; acc.w *= nd;
    g_agg4[(size_t)warp * 32 + lane] = acc;
}

// ---------------- K6: fused GEMM + LayerNorm + ReLU + skip GEMM ------------
// 256 threads/block, 32 nodes/block. Thread (c4 = tid&63, ng = tid>>6) owns
// columns [4*c4, 4*c4+4) for 8 nodes [ng*8, ng*8+8): 64 fp32 accumulators.
__global__ __launch_bounds__(256) void k_fused(
    const float* __restrict__ features,
    const float* __restrict__ W,
    const float* __restrict__ b,
    const float* __restrict__ gamma,
    const float* __restrict__ beta,
    const float* __restrict__ skip_W,
    const float* __restrict__ skip_b,
    float* __restrict__ out) {
    __shared__ float pool[8192];     // 32KB: s_a[32][128] | s_f[32][128]
    __shared__ float s_stats[32][2]; // per-node {mu, inv}
    float* s_a = pool;
    float* s_f = pool + 4096;

    int tid = threadIdx.x;
    int c4 = tid & 63;
    int ng = tid >> 6;
    int nb = ng * 8;                 // first local node of this thread
    int base_node = blockIdx.x * 32; // N_NODES % 32 == 0

    // Stage agg (already norm_dst-scaled) and features into smem.
    const float4* feat4 = reinterpret_cast<const float4*>(features);
#pragma unroll
    for (int i = 0; i < 4; i++) {
        int idx = tid + i * 256;     // 0..1023 over (node, col4)
        reinterpret_cast<float4*>(s_a)[idx] = g_agg4[(size_t)base_node * 32 + idx];
        reinterpret_cast<float4*>(s_f)[idx] = feat4[(size_t)base_node * 32 + idx];
    }
    __syncthreads();

    const float4* W4  = reinterpret_cast<const float4*>(W);
    const float4* SW4 = reinterpret_cast<const float4*>(skip_W);
    float4 bb = reinterpret_cast<const float4*>(b)[c4];
    float4 sb = reinterpret_cast<const float4*>(skip_b)[c4];
    float4 acc[8], sac[8];
#pragma unroll
    for (int n = 0; n < 8; n++) { acc[n] = bb; sac[n] = sb; }

#pragma unroll 4
    for (int k = 0; k < IN_DIM; k++) {
        float4 w  = W4[k * (HID_DIM / 4) + c4];
        float4 sw = SW4[k * (HID_DIM / 4) + c4];
#pragma unroll
        for (int n = 0; n < 8; n++) {
            float a = s_a[(nb + n) * IN_DIM + k];   // broadcast LDS
            float f = s_f[(nb + n) * IN_DIM + k];
            acc[n].x += a * w.x;  acc[n].y += a * w.y;
            acc[n].z += a * w.z;  acc[n].w += a * w.w;
            sac[n].x += f * sw.x; sac[n].y += f * sw.y;
            sac[n].z += f * sw.z; sac[n].w += f * sw.w;
        }
    }

    // ----- LayerNorm: per-node mean/var over 256 cols -----
    __syncthreads();  // done reading s_a/s_f; reuse pool for partials
#pragma unroll
    for (int n = 0; n < 8; n++) {
        float s = acc[n].x + acc[n].y + acc[n].z + acc[n].w;
        float q = acc[n].x * acc[n].x + acc[n].y * acc[n].y
                + acc[n].z * acc[n].z + acc[n].w * acc[n].w;
        pool[(nb + n) * 64 + c4] = s;
        pool[4096 + (nb + n) * 64 + c4] = q;
    }
    __syncthreads();

    int warp = tid >> 5, lane = tid & 31;
#pragma unroll
    for (int i = 0; i < 4; i++) {
        int n = i * 8 + warp;  // one warp reduces one node per iteration
        float s = pool[n * 64 + lane] + pool[n * 64 + lane + 32];
        float q = pool[4096 + n * 64 + lane] + pool[4096 + n * 64 + lane + 32];
#pragma unroll
        for (int o = 16; o > 0; o >>= 1) {
            s += __shfl_xor_sync(0xFFFFFFFFu, s, o);
            q += __shfl_xor_sync(0xFFFFFFFFu, q, o);
        }
        if (lane == 0) {
            float mu = s * (1.0f / HID_DIM);
            float var = q * (1.0f / HID_DIM) - mu * mu;
            s_stats[n][0] = mu;
            s_stats[n][1] = rsqrtf(var + LN_EPS);
        }
    }
    __syncthreads();

    float4 gm = reinterpret_cast<const float4*>(gamma)[c4];
    float4 bt = reinterpret_cast<const float4*>(beta)[c4];
#pragma unroll
    for (int n = 0; n < 8; n++) {
        float mu  = s_stats[nb + n][0];
        float inv = s_stats[nb + n][1];
        float4 o;
        o.x = fmaxf((acc[n].x - mu) * inv * gm.x + bt.x, 0.0f) + sac[n].x;
        o.y = fmaxf((acc[n].y - mu) * inv * gm.y + bt.y, 0.0f) + sac[n].y;
        o.z = fmaxf((acc[n].z - mu) * inv * gm.z + bt.z, 0.0f) + sac[n].z;
        o.w = fmaxf((acc[n].w - mu) * inv * gm.w + bt.w, 0.0f) + sac[n].w;
        reinterpret_cast<float4*>(out)[(size_t)(base_node + nb + n) * (HID_DIM / 4) + c4] = o;
    }
}

// ---------------- launch ----------------------------------------------------
extern "C" void kernel_launch(void* const* d_in, const int* in_sizes, int n_in,
                              void* d_out, int out_size) {
    const float* features = (const float*)d_in[0];
    const int*   src      = (const int*)d_in[1];   // JAX x64-off: int32
    const int*   dst      = (const int*)d_in[2];   // JAX x64-off: int32
    const float* W        = (const float*)d_in[3];
    const float* b        = (const float*)d_in[4];
    const float* gamma    = (const float*)d_in[5];
    const float* beta     = (const float*)d_in[6];
    const float* skip_W   = (const float*)d_in[7];
    const float* skip_b   = (const float*)d_in[8];
    float* out = (float*)d_out;

    const int n4 = N_NODES * (IN_DIM / 4);

    k_zero<<<(N_NODES + 255) / 256, 256>>>();
    k_degree<<<(N_EDGES / 2 + 255) / 256, 256>>>(src, dst);
    k_scan<<<1, 1024>>>();
    k_fill<<<(N_EDGES / 2 + 255) / 256, 256>>>(src, dst);
    k_scale<<<(n4 + 255) / 256, 256>>>(features);
    k_gather<<<(N_NODES + 7) / 8, 256>>>();          // warp per dst node
    k_fused<<<N_NODES / 32, 256>>>(features, W, b, gamma, beta,
                                   skip_W, skip_b, out);
}

// round 10
// speedup vs baseline: 1.0022x; 1.0022x over previous
#include <cuda_runtime.h>
#include <cuda_bf16.h>
#include <cstdint>

#define N_NODES 100000
#define N_EDGES 1600000
#define IN_DIM 128
#define HID_DIM 256
#define LN_EPS 1e-5f

// ---------------- scratch (device globals: no runtime allocation) ----------
__device__ float4 g_h4[N_NODES * 32];      // h = features * norm_src
__device__ float4 g_agg4[N_NODES * 32];    // segsum(h[src],dst)*norm_dst
__device__ int g_deg_out[N_NODES];
__device__ int g_deg_in[N_NODES];
__device__ int g_row_start[N_NODES];
__device__ int g_cursor[N_NODES];
__device__ int g_col[N_EDGES];

// ---------------- f32x2 packed-math helpers (sm_100-family base ISA) --------
typedef unsigned long long ull;
__device__ __forceinline__ ull f2pack(float lo, float hi) {
    ull d;
    asm("mov.b64 %0, {%1, %2};" : "=l"(d) : "f"(lo), "f"(hi));
    return d;
}
__device__ __forceinline__ ull fma2(ull a, ull b, ull c) {
    ull d;
    asm("fma.rn.f32x2 %0, %1, %2, %3;" : "=l"(d) : "l"(a), "l"(b), "l"(c));
    return d;
}
__device__ __forceinline__ float f2sum(ull v) {
    float lo, hi;
    asm("mov.b64 {%0, %1}, %2;" : "=f"(lo), "=f"(hi) : "l"(v));
    return lo + hi;
}

// ---------------- K0: zero counters ----------------------------------------
__global__ void k_zero() {
    int i = blockIdx.x * blockDim.x + threadIdx.x;
    if (i < N_NODES) { g_deg_out[i] = 0; g_deg_in[i] = 0; g_cursor[i] = 0; }
}

// ---------------- K1: degree histograms (2 edges/thread) --------------------
__global__ void k_degree(const int* __restrict__ src, const int* __restrict__ dst) {
    int t = blockIdx.x * blockDim.x + threadIdx.x;
    if (t * 2 >= N_EDGES) return;
    int2 s2 = reinterpret_cast<const int2*>(src)[t];
    int2 d2 = reinterpret_cast<const int2*>(dst)[t];
    atomicAdd(&g_deg_out[s2.x], 1);
    atomicAdd(&g_deg_out[s2.y], 1);
    atomicAdd(&g_deg_in[d2.x], 1);
    atomicAdd(&g_deg_in[d2.y], 1);
}

// ---------------- K2: exclusive scan of deg_in -> row_start (1 block) -------
__global__ __launch_bounds__(1024) void k_scan() {
    __shared__ int s_part[1024];
    const int CH = (N_NODES + 1023) / 1024;
    int tid = threadIdx.x;
    int begin = tid * CH;
    int end = begin + CH; if (end > N_NODES) end = N_NODES;
    int sum = 0;
    for (int i = begin; i < end; i++) sum += g_deg_in[i];
    s_part[tid] = sum;
    __syncthreads();
    for (int off = 1; off < 1024; off <<= 1) {
        int t = (tid >= off) ? s_part[tid - off] : 0;
        __syncthreads();
        if (tid >= off) s_part[tid] += t;
        __syncthreads();
    }
    int run = s_part[tid] - sum;
    for (int i = begin; i < end; i++) { g_row_start[i] = run; run += g_deg_in[i]; }
}

// ---------------- K3: CSR fill (2 edges/thread, int atomics) ----------------
__global__ void k_fill(const int* __restrict__ src, const int* __restrict__ dst) {
    int t = blockIdx.x * blockDim.x + threadIdx.x;
    if (t * 2 >= N_EDGES) return;
    int2 s2 = reinterpret_cast<const int2*>(src)[t];
    int2 d2 = reinterpret_cast<const int2*>(dst)[t];
    int p0 = atomicAdd(&g_cursor[d2.x], 1);
    int p1 = atomicAdd(&g_cursor[d2.y], 1);
    g_col[g_row_start[d2.x] + p0] = s2.x;
    g_col[g_row_start[d2.y] + p1] = s2.y;
}

// ---------------- K4: h = features * rsqrt(max(deg_out,1)) ------------------
__global__ void k_scale(const float* __restrict__ features) {
    int i = blockIdx.x * blockDim.x + threadIdx.x;
    const int total = N_NODES * 32;
    if (i >= total) return;
    int node = i >> 5;
    float ns = rsqrtf(fmaxf((float)g_deg_out[node], 1.0f));
    float4 v = reinterpret_cast<const float4*>(features)[i];
    v.x *= ns; v.y *= ns; v.z *= ns; v.w *= ns;
    g_h4[i] = v;
}

// ---------------- K5: gather SpMM, warp per dst node ------------------------
__global__ __launch_bounds__(256) void k_gather() {
    int warp = (blockIdx.x * blockDim.x + threadIdx.x) >> 5;
    int lane = threadIdx.x & 31;
    if (warp >= N_NODES) return;
    int deg = g_deg_in[warp];
    int base = g_row_start[warp];
    float4 acc = make_float4(0.f, 0.f, 0.f, 0.f);
    int k = 0;
    for (; k + 4 <= deg; k += 4) {
        int e0 = g_col[base + k], e1 = g_col[base + k + 1];
        int e2 = g_col[base + k + 2], e3 = g_col[base + k + 3];
        float4 a = g_h4[(size_t)e0 * 32 + lane];
        float4 b = g_h4[(size_t)e1 * 32 + lane];
        float4 c = g_h4[(size_t)e2 * 32 + lane];
        float4 d = g_h4[(size_t)e3 * 32 + lane];
        acc.x += (a.x + b.x) + (c.x + d.x);
        acc.y += (a.y + b.y) + (c.y + d.y);
        acc.z += (a.z + b.z) + (c.z + d.z);
        acc.w += (a.w + b.w) + (c.w + d.w);
    }
    for (; k < deg; k++) {
        int e = g_col[base + k];
        float4 a = g_h4[(size_t)e * 32 + lane];
        acc.x += a.x; acc.y += a.y; acc.z += a.z; acc.w += a.w;
    }
    float nd = rsqrtf(fmaxf((float)deg, 1.0f));
    acc.x *= nd; acc.y *= nd; acc.z *= nd; acc.w *= nd;
    g_agg4[(size_t)warp * 32 + lane] = acc;
}

// ---------------- K6: fused GEMM + LN + ReLU + skip, packed f32x2 -----------
// 512 threads/block, 32 nodes/block. Thread (c4 = tid&63, ng = tid>>6) owns
// columns [4*c4, 4*c4+4) for 4 nodes [ng*4, ng*4+4).
// k is processed in pairs; each (node,col) accumulator is an f32x2 holding
// (even-k partial, odd-k partial), combined scalar at the end (exact fp32 FMA).
__global__ __launch_bounds__(512, 1) void k_fused(
    const float* __restrict__ features,
    const float* __restrict__ W,
    const float* __restrict__ b,
    const float* __restrict__ gamma,
    const float* __restrict__ beta,
    const float* __restrict__ skip_W,
    const float* __restrict__ skip_b,
    float* __restrict__ out) {
    __shared__ float s_a[32][IN_DIM];
    __shared__ float s_f[32][IN_DIM];
    __shared__ float s_sum[32][64];
    __shared__ float s_sq[32][64];
    __shared__ float s_st[32][2];

    int tid = threadIdx.x;
    int c4 = tid & 63;
    int ng = tid >> 6;       // 0..7
    int nb = ng * 4;         // first of this thread's 4 nodes
    int base_node = blockIdx.x * 32;

    // Stage agg + features tiles (1024 float4 each).
    const float4* feat4 = reinterpret_cast<const float4*>(features);
#pragma unroll
    for (int i = 0; i < 2; i++) {
        int idx = tid + i * 512;
        reinterpret_cast<float4*>(s_a)[idx] = g_agg4[(size_t)base_node * 32 + idx];
        reinterpret_cast<float4*>(s_f)[idx] = feat4[(size_t)base_node * 32 + idx];
    }
    __syncthreads();

    const float4* W4  = reinterpret_cast<const float4*>(W);
    const float4* SW4 = reinterpret_cast<const float4*>(skip_W);
    float4 bb = reinterpret_cast<const float4*>(b)[c4];
    float4 sbb = reinterpret_cast<const float4*>(skip_b)[c4];

    ull acc[4][4], sac[4][4];
#pragma unroll
    for (int n = 0; n < 4; n++) {
        acc[n][0] = f2pack(bb.x, 0.f);  acc[n][1] = f2pack(bb.y, 0.f);
        acc[n][2] = f2pack(bb.z, 0.f);  acc[n][3] = f2pack(bb.w, 0.f);
        sac[n][0] = f2pack(sbb.x, 0.f); sac[n][1] = f2pack(sbb.y, 0.f);
        sac[n][2] = f2pack(sbb.z, 0.f); sac[n][3] = f2pack(sbb.w, 0.f);
    }

#pragma unroll 4
    for (int kp = 0; kp < IN_DIM / 2; kp++) {
        float4 w0 = W4[(2 * kp) * 64 + c4];
        float4 w1 = W4[(2 * kp + 1) * 64 + c4];
        float4 t0 = SW4[(2 * kp) * 64 + c4];
        float4 t1 = SW4[(2 * kp + 1) * 64 + c4];
        ull wx = f2pack(w0.x, w1.x), wy = f2pack(w0.y, w1.y);
        ull wz = f2pack(w0.z, w1.z), ww = f2pack(w0.w, w1.w);
        ull tx = f2pack(t0.x, t1.x), ty = f2pack(t0.y, t1.y);
        ull tz = f2pack(t0.z, t1.z), tw = f2pack(t0.w, t1.w);
#pragma unroll
        for (int n = 0; n < 4; n++) {
            ull a2 = *reinterpret_cast<const ull*>(&s_a[nb + n][2 * kp]); // LDS.64 bcast
            ull f2 = *reinterpret_cast<const ull*>(&s_f[nb + n][2 * kp]);
            acc[n][0] = fma2(a2, wx, acc[n][0]);
            acc[n][1] = fma2(a2, wy, acc[n][1]);
            acc[n][2] = fma2(a2, wz, acc[n][2]);
            acc[n][3] = fma2(a2, ww, acc[n][3]);
            sac[n][0] = fma2(f2, tx, sac[n][0]);
            sac[n][1] = fma2(f2, ty, sac[n][1]);
            sac[n][2] = fma2(f2, tz, sac[n][2]);
            sac[n][3] = fma2(f2, tw, sac[n][3]);
        }
    }

    // Collapse pairs to scalars.
    float av[4][4], sv[4][4];
#pragma unroll
    for (int n = 0; n < 4; n++)
#pragma unroll
        for (int c = 0; c < 4; c++) { av[n][c] = f2sum(acc[n][c]); sv[n][c] = f2sum(sac[n][c]); }

    // LN partials: per node, per c4: sum / sumsq of this thread's 4 cols.
#pragma unroll
    for (int n = 0; n < 4; n++) {
        float s = av[n][0] + av[n][1] + av[n][2] + av[n][3];
        float q = av[n][0] * av[n][0] + av[n][1] * av[n][1]
                + av[n][2] * av[n][2] + av[n][3] * av[n][3];
        s_sum[nb + n][c4] = s;
        s_sq[nb + n][c4] = q;
    }
    __syncthreads();

    int warp = tid >> 5, lane = tid & 31;
#pragma unroll
    for (int i = 0; i < 2; i++) {
        int n = warp * 2 + i;  // 16 warps x 2 nodes
        float s = s_sum[n][lane] + s_sum[n][lane + 32];
        float q = s_sq[n][lane] + s_sq[n][lane + 32];
#pragma unroll
        for (int o = 16; o > 0; o >>= 1) {
            s += __shfl_xor_sync(0xFFFFFFFFu, s, o);
            q += __shfl_xor_sync(0xFFFFFFFFu, q, o);
        }
        if (lane == 0) {
            float mu = s * (1.0f / HID_DIM);
            float var = q * (1.0f / HID_DIM) - mu * mu;
            s_st[n][0] = mu;
            s_st[n][1] = rsqrtf(var + LN_EPS);
        }
    }
    __syncthreads();

    float4 gm = reinterpret_cast<const float4*>(gamma)[c4];
    float4 bt = reinterpret_cast<const float4*>(beta)[c4];
#pragma unroll
    for (int n = 0; n < 4; n++) {
        float mu = s_st[nb + n][0], inv = s_st[nb + n][1];
        float4 o;
        o.x = fmaxf((av[n][0] - mu) * inv * gm.x + bt.x, 0.f) + sv[n][0];
        o.y = fmaxf((av[n][1] - mu) * inv * gm.y + bt.y, 0.f) + sv[n][1];
        o.z = fmaxf((av[n][2] - mu) * inv * gm.z + bt.z, 0.f) + sv[n][2];
        o.w = fmaxf((av[n][3] - mu) * inv * gm.w + bt.w, 0.f) + sv[n][3];
        reinterpret_cast<float4*>(out)[(size_t)(base_node + nb + n) * 64 + c4] = o;
    }
}

// ---------------- launch ----------------------------------------------------
extern "C" void kernel_launch(void* const* d_in, const int* in_sizes, int n_in,
                              void* d_out, int out_size) {
    const float* features = (const float*)d_in[0];
    const int*   src      = (const int*)d_in[1];   // JAX x64-off: int32
    const int*   dst      = (const int*)d_in[2];
    const float* W        = (const float*)d_in[3];
    const float* b        = (const float*)d_in[4];
    const float* gamma    = (const float*)d_in[5];
    const float* beta     = (const float*)d_in[6];
    const float* skip_W   = (const float*)d_in[7];
    const float* skip_b   = (const float*)d_in[8];
    float* out = (float*)d_out;

    const int n4 = N_NODES * 32;

    k_zero<<<(N_NODES + 255) / 256, 256>>>();
    k_degree<<<(N_EDGES / 2 + 255) / 256, 256>>>(src, dst);
    k_scan<<<1, 1024>>>();
    k_fill<<<(N_EDGES / 2 + 255) / 256, 256>>>(src, dst);
    k_scale<<<(n4 + 255) / 256, 256>>>(features);
    k_gather<<<(N_NODES + 7) / 8, 256>>>();
    k_fused<<<N_NODES / 32, 512>>>(features, W, b, gamma, beta,
                                   skip_W, skip_b, out);
}